// round 10
// baseline (speedup 1.0000x reference)
#include <cuda_runtime.h>
#include <math.h>
#include <float.h>

// Divisive normalization over time — single streaming pass.
//   y1 recurrence (A,Bm); z2 = conv(y1,a2); max(y1) cancels in norm:
//   norm[t] = z2[t]/max z2.  drive[t] = y1[t]/max y1.
//   out = nan_to_num(|drive^n| / (|norm^n| + sigma)) at t_sel.
//
// R8 -> R9:
//  * 2 pixels/thread (float2) instead of 4: doubles warps/SM (13.8 -> 27.7),
//    occupancy was grid-limited at 20.6% and issue only 44.8%.
//  * t==tt capture hoisted out of the steady-state body: tt is warp-uniform,
//    so only the one 8-step block containing tt runs the capture variant.
//    Steady state has zero SETP/FSEL overhead (~25% fewer instrs/step).

#define PF 8

__global__ __launch_bounds__(64) void divnorm_kernel(
    const float* __restrict__ x,      // (T, P)
    const float* __restrict__ tau1,   // (CWH)
    const float* __restrict__ tau2,   // (CWH)
    const float* __restrict__ sigma,  // (CWH)
    const float* __restrict__ nexp,   // (CWH)
    const int*   __restrict__ t_sel,  // scalar
    float*       __restrict__ out,    // (P)
    int P2, int T, int CWH)
{
    int tid = blockIdx.x * blockDim.x + threadIdx.x;
    if (tid >= P2) return;
    const int p   = tid * 2;
    const int cwh = p % CWH;              // CWH % 2 == 0: pair never crosses batch boundary
    const int tt  = *t_sel;

    const float2 t1 = *reinterpret_cast<const float2*>(tau1 + cwh);
    const float2 t2 = *reinterpret_cast<const float2*>(tau2 + cwh);

    float a1[2], a2[2];
    a1[0] = expf(-1.0f / t1.x); a1[1] = expf(-1.0f / t1.y);
    a2[0] = expf(-1.0f / t2.x); a2[1] = expf(-1.0f / t2.y);

    float A[2], Bm[2], c[2], my1[2], mz2[2], y1s[2], z2s[2];
#pragma unroll
    for (int i = 0; i < 2; ++i) {
        A[i] = 0.0f; Bm[i] = 0.0f; c[i] = 0.0f;
        my1[i] = -FLT_MAX; mz2[i] = -FLT_MAX;
        y1s[i] = 0.0f; z2s[i] = 0.0f;
    }

    // One recurrence step consuming xv. No select logic.
    auto step = [&](const float2& xv) {
        const float xs[2] = {xv.x, xv.y};
#pragma unroll
        for (int i = 0; i < 2; ++i) {
            const float y1 = Bm[i];                  // scan output at t (entry value)
            const float z2 = c[i];
            const float nA = fmaf(a1[i], A[i], xs[i]);
            const float nB = a1[i] * (Bm[i] + A[i]); // uses OLD A
            c[i]   = fmaf(a2[i], c[i], y1);
            my1[i] = fmaxf(my1[i], y1);
            mz2[i] = fmaxf(mz2[i], z2);
            A[i] = nA; Bm[i] = nB;
        }
    };
    // Snapshot state at entry of step t == tt: Bm == y1[tt], c == z2[tt].
    auto snap = [&]() {
#pragma unroll
        for (int i = 0; i < 2; ++i) { y1s[i] = Bm[i]; z2s[i] = c[i]; }
    };

    const float2* __restrict__ xp = reinterpret_cast<const float2*>(x) + tid;

    // ---- prologue: prime PF unconditional loads (T >= 2*PF; T=128) ----
    float2 buf[PF];
#pragma unroll
    for (int u = 0; u < PF; ++u) {
        buf[u] = __ldg(xp);
        xp += P2;
    }

    // ---- steady state ----
    int t0 = 0;
    for (; t0 + 2 * PF <= T; t0 += PF) {
        if ((unsigned)(tt - t0) < (unsigned)PF) {
            // rare block: contains the capture step (warp-uniform branch)
#pragma unroll
            for (int u = 0; u < PF; ++u) {
                const float2 xv = buf[u];
                buf[u] = __ldg(xp);
                xp += P2;
                if (t0 + u == tt) snap();
                step(xv);
            }
        } else {
            // common block: no selects at all
#pragma unroll
            for (int u = 0; u < PF; ++u) {
                const float2 xv = buf[u];
                buf[u] = __ldg(xp);
                xp += P2;
                step(xv);
            }
        }
    }

    // ---- epilogue: last (T - t0) <= PF steps ----
#pragma unroll
    for (int u = 0; u < PF; ++u) {
        if (t0 + u < T) {
            if (t0 + u == tt) snap();
            step(buf[u]);
        }
    }

    const float2 sg = *reinterpret_cast<const float2*>(sigma + cwh);
    const float2 nv = *reinterpret_cast<const float2*>(nexp + cwh);
    const float sgs[2] = {sg.x, sg.y};
    const float nvs[2] = {nv.x, nv.y};

    float2 ov;
    float* ovp = reinterpret_cast<float*>(&ov);
#pragma unroll
    for (int i = 0; i < 2; ++i) {
        const float drive = y1s[i] / my1[i];
        const float nrm   = z2s[i] / mz2[i];
        const float id    = fabsf(powf(drive, nvs[i]));
        const float nr    = fabsf(powf(nrm,  nvs[i])) + sgs[i];
        float r = id / nr;
        // nan_to_num semantics
        if (isnan(r))      r = 0.0f;
        else if (isinf(r)) r = (r > 0.0f) ? FLT_MAX : -FLT_MAX;
        ovp[i] = r;
    }
    *reinterpret_cast<float2*>(out + p) = ov;
}

extern "C" void kernel_launch(void* const* d_in, const int* in_sizes, int n_in,
                              void* d_out, int out_size)
{
    const float* x     = (const float*)d_in[0];
    const float* tau1  = (const float*)d_in[1];
    const float* tau2  = (const float*)d_in[2];
    const float* sigma = (const float*)d_in[3];
    const float* nexp  = (const float*)d_in[4];
    const int*   t_sel = (const int*)  d_in[5];
    float* out = (float*)d_out;

    const int P   = out_size;               // B*C*W*H = 262144
    const int T   = in_sizes[0] / P;        // 128
    const int CWH = in_sizes[3];            // 32768
    const int P2  = P / 2;

    const int threads = 64;
    const int blocks  = (P2 + threads - 1) / threads;
    divnorm_kernel<<<blocks, threads>>>(x, tau1, tau2, sigma, nexp, t_sel, out,
                                        P2, T, CWH);
}